// round 13
// baseline (speedup 1.0000x reference)
#include <cuda_runtime.h>
#include <cuda_fp16.h>
#include <cstdint>

// FeatureVolume: trilinear grid_sample of fm [32, 129, 129, 129] at 1M coords in [-1,1].
// R11: transpose at LTS cap (63.6us). Sample stuck at 93us / 72% DRAM because random
// point order gives voxel-reuse distance ~ the whole stream -> L2 can't capture it.
// This round: counting-sort points into 289 (z,y) bins before sampling. Concurrent
// wave then touches ~7MB of volume -> L2-resident gathers, DRAM ~= cold fill.

#define FV_S    129
#define FV_DHW  (129 * 129 * 129)  // 2,146,689 voxels
#define FV_C    32
#define TVOX    128                // voxels per transpose block
#define NBINS   (17 * 17)          // (z0>>3, y0>>3) coarse cells
#define MAXPTS  1048576

// Channel-last fp16 scratch: ~131 MB (device bss).
__device__ __half g_fmT[(size_t)FV_DHW * FV_C];
// Binning scratch.
__device__ unsigned g_hist[NBINS];
__device__ unsigned g_cursor[NBINS];
__device__ uint4    g_sorted[MAXPTS];   // x,y,z coord bits + original point index

// ---------------------------------------------------------------------------
// Transpose [C, DHW] fp32 -> [DHW, C] fp16 via a 32ch x 128vox smem tile.
// ---------------------------------------------------------------------------
__global__ __launch_bounds__(256) void fv_transpose_kernel(const float* __restrict__ fm) {
    __shared__ float tile[32][TVOX + 1];
    const int v0 = blockIdx.x * TVOX;
    const int tx = threadIdx.x;             // 0..31
    const int ty = threadIdx.y;             // 0..7

    #pragma unroll
    for (int i = 0; i < 4; i++) {
        const int c = ty + i * 8;
        #pragma unroll
        for (int j = 0; j < 4; j++) {
            const int vloc = tx + 32 * j;
            const int v = v0 + vloc;
            tile[c][vloc] = (v < FV_DHW) ? fm[(size_t)c * FV_DHW + v] : 0.0f;
        }
    }
    __syncthreads();

    __half2* __restrict__ outp = reinterpret_cast<__half2*>(g_fmT);
    const int c2 = tx & 15;
    const int vh = tx >> 4;
    #pragma unroll
    for (int s = 0; s < 4; s++) {
        #pragma unroll
        for (int i = 0; i < 2; i++) {
            const int vloc = s * 32 + ty + i * 16 + (vh << 3);
            const int v = v0 + vloc;
            if (v < FV_DHW) {
                const float2 f2 = make_float2(tile[2 * c2][vloc], tile[2 * c2 + 1][vloc]);
                outp[(size_t)v * 16 + c2] = __float22half2_rn(f2);
            }
        }
    }
}

// ---------------------------------------------------------------------------
// Binning: counting sort of points by coarse (z, y) cell.
// ---------------------------------------------------------------------------
static __device__ __forceinline__ int fv_bin(float cy, float cz) {
    const float fy = fminf(fmaxf((cy + 1.0f) * 64.0f, 0.0f), 128.0f);
    const float fz = fminf(fmaxf((cz + 1.0f) * 64.0f, 0.0f), 128.0f);
    const int y0 = (int)fy;                 // floor (nonneg)
    const int z0 = (int)fz;
    return (z0 >> 3) * 17 + (y0 >> 3);      // 17x17 bins
}

__global__ void fv_zero_kernel() {
    const int i = threadIdx.x;
    if (i < NBINS) g_hist[i] = 0u;
}

__global__ __launch_bounds__(256) void fv_hist_kernel(const float* __restrict__ xs, int n) {
    const int p = blockIdx.x * blockDim.x + threadIdx.x;
    if (p >= n) return;
    const float cy = __ldcs(xs + 3 * (size_t)p + 1);
    const float cz = __ldcs(xs + 3 * (size_t)p + 2);
    atomicAdd(&g_hist[fv_bin(cy, cz)], 1u);
}

__global__ __launch_bounds__(512) void fv_scan_kernel() {
    __shared__ unsigned s[512];
    const int t = threadIdx.x;              // blockDim = 512 >= NBINS
    const unsigned v = (t < NBINS) ? g_hist[t] : 0u;
    s[t] = v;
    __syncthreads();
    #pragma unroll
    for (int off = 1; off < 512; off <<= 1) {
        const unsigned add = (t >= off) ? s[t - off] : 0u;
        __syncthreads();
        s[t] += add;
        __syncthreads();
    }
    if (t < NBINS) g_cursor[t] = s[t] - v;  // exclusive prefix
}

__global__ __launch_bounds__(256) void fv_scatter_kernel(const float* __restrict__ xs, int n) {
    const int p = blockIdx.x * blockDim.x + threadIdx.x;
    if (p >= n) return;
    const float cx = __ldcs(xs + 3 * (size_t)p + 0);
    const float cy = __ldcs(xs + 3 * (size_t)p + 1);
    const float cz = __ldcs(xs + 3 * (size_t)p + 2);
    const unsigned slot = atomicAdd(&g_cursor[fv_bin(cy, cz)], 1u);
    g_sorted[slot] = make_uint4(__float_as_uint(cx), __float_as_uint(cy),
                                __float_as_uint(cz), (unsigned)p);
}

// ---------------------------------------------------------------------------
// Sample (sorted order): 8 threads per sorted point; thread g owns channels
// [4g, 4g+4). Corner = 64B record; each thread one LDG.64. Output scattered to
// the ORIGINAL point index (full 128B line) with streaming store.
// ---------------------------------------------------------------------------
static __device__ __forceinline__ void fv_acc_corner(
    float4& acc, const uint2* __restrict__ f, int vox, float wgt
) {
    uint2 u = __ldg(&f[(size_t)vox * 8]);
    const __half2 h0 = *reinterpret_cast<const __half2*>(&u.x);
    const __half2 h1 = *reinterpret_cast<const __half2*>(&u.y);
    const float2 a = __half22float2(h0);
    const float2 b = __half22float2(h1);
    acc.x = fmaf(wgt, a.x, acc.x);
    acc.y = fmaf(wgt, a.y, acc.y);
    acc.z = fmaf(wgt, b.x, acc.z);
    acc.w = fmaf(wgt, b.y, acc.w);
}

__global__ __launch_bounds__(256) void fv_sample_kernel(
    float4* __restrict__ out,       // [N, 8] float4 == [N, 32] float
    int n
) {
    const int t = blockIdx.x * blockDim.x + threadIdx.x;
    const int i = t >> 3;                   // sorted slot
    const int g = t & 7;                    // channel group
    if (i >= n) return;

    const uint4 s = g_sorted[i];            // warp-deduped broadcast load
    const float cx = __uint_as_float(s.x);  // -> W
    const float cy = __uint_as_float(s.y);  // -> H
    const float cz = __uint_as_float(s.z);  // -> D
    const unsigned p = s.w;                 // original point index

    const float fx = fminf(fmaxf((cx + 1.0f) * 64.0f, 0.0f), 128.0f);
    const float fy = fminf(fmaxf((cy + 1.0f) * 64.0f, 0.0f), 128.0f);
    const float fz = fminf(fmaxf((cz + 1.0f) * 64.0f, 0.0f), 128.0f);

    const int x0 = (int)floorf(fx);
    const int y0 = (int)floorf(fy);
    const int z0 = (int)floorf(fz);
    const float tx = fx - (float)x0;
    const float ty = fy - (float)y0;
    const float tz = fz - (float)z0;
    const int x1 = min(x0 + 1, 128);
    const int y1 = min(y0 + 1, 128);
    const int z1 = min(z0 + 1, 128);

    const float wx0 = 1.0f - tx, wx1 = tx;
    const float wy0 = 1.0f - ty, wy1 = ty;
    const float wz0 = 1.0f - tz, wz1 = tz;

    const int r00 = (z0 * FV_S + y0) * FV_S;
    const int r01 = (z0 * FV_S + y1) * FV_S;
    const int r10 = (z1 * FV_S + y0) * FV_S;
    const int r11 = (z1 * FV_S + y1) * FV_S;

    const uint2* __restrict__ f = reinterpret_cast<const uint2*>(g_fmT) + g;

    float4 acc = make_float4(0.0f, 0.0f, 0.0f, 0.0f);
    fv_acc_corner(acc, f, r00 + x0, wz0 * wy0 * wx0);
    fv_acc_corner(acc, f, r00 + x1, wz0 * wy0 * wx1);
    fv_acc_corner(acc, f, r01 + x0, wz0 * wy1 * wx0);
    fv_acc_corner(acc, f, r01 + x1, wz0 * wy1 * wx1);
    fv_acc_corner(acc, f, r10 + x0, wz1 * wy0 * wx0);
    fv_acc_corner(acc, f, r10 + x1, wz1 * wy0 * wx1);
    fv_acc_corner(acc, f, r11 + x0, wz1 * wy1 * wx0);
    fv_acc_corner(acc, f, r11 + x1, wz1 * wy1 * wx1);

    __stcs(&out[(size_t)p * 8 + g], acc);   // streaming scatter, full 128B line/point
}

extern "C" void kernel_launch(void* const* d_in, const int* in_sizes, int n_in,
                              void* d_out, int out_size) {
    const float* x  = (const float*)d_in[0];   // [N, 3]
    const float* fm = (const float*)d_in[1];   // [32, 129, 129, 129]
    const int n = in_sizes[0] / 3;

    // 1) Transpose + fp16 quantize to channel-last scratch.
    fv_transpose_kernel<<<(FV_DHW + TVOX - 1) / TVOX, dim3(32, 8)>>>(fm);

    // 2) Counting sort of points by coarse (z, y) cell.
    fv_zero_kernel<<<1, 512>>>();
    fv_hist_kernel<<<(n + 255) / 256, 256>>>(x, n);
    fv_scan_kernel<<<1, 512>>>();
    fv_scatter_kernel<<<(n + 255) / 256, 256>>>(x, n);

    // 3) Gather + trilinear blend in sorted (spatially local) order.
    const int total = n * 8;
    fv_sample_kernel<<<(total + 255) / 256, 256>>>((float4*)d_out, n);
}

// round 15
// speedup vs baseline: 2.3162x; 2.3162x over previous
#include <cuda_runtime.h>
#include <cuda_fp16.h>
#include <cstdint>

// FeatureVolume: trilinear grid_sample of fm [32, 129, 129, 129] at 1M coords in [-1,1].
// R13 post-mortem: counting-sort binning regressed 157->589us (unattributed; model
// wrong) -> reverted. This round keeps the 156.7us champion structure and gets
// gather locality WITHOUT sorting: 4 z-slab passes of the sampler. Per-pass hot
// set = 33MB slab + 32MB out-stream + 12MB coords ~= 77MB < 126MB L2, so the
// ~3.8x voxel reuse becomes L2 hits. Out-of-slab point groups exit immediately.

#define FV_S    129
#define FV_DHW  (129 * 129 * 129)  // 2,146,689 voxels
#define FV_C    32
#define TVOX    128                // voxels per transpose block

// Channel-last fp16 scratch: ~131 MB (device bss).
__device__ __half g_fmT[(size_t)FV_DHW * FV_C];

// ---------------------------------------------------------------------------
// Transpose [C, DHW] fp32 -> [DHW, C] fp16 via a 32ch x 128vox smem tile.
// (Unchanged from the 156.7us champion: measured at the LTS cap, 63.6us.)
// ---------------------------------------------------------------------------
__global__ __launch_bounds__(256) void fv_transpose_kernel(const float* __restrict__ fm) {
    __shared__ float tile[32][TVOX + 1];
    const int v0 = blockIdx.x * TVOX;
    const int tx = threadIdx.x;             // 0..31
    const int ty = threadIdx.y;             // 0..7

    #pragma unroll
    for (int i = 0; i < 4; i++) {
        const int c = ty + i * 8;
        #pragma unroll
        for (int j = 0; j < 4; j++) {
            const int vloc = tx + 32 * j;
            const int v = v0 + vloc;
            tile[c][vloc] = (v < FV_DHW) ? fm[(size_t)c * FV_DHW + v] : 0.0f;
        }
    }
    __syncthreads();

    __half2* __restrict__ outp = reinterpret_cast<__half2*>(g_fmT);
    const int c2 = tx & 15;
    const int vh = tx >> 4;
    #pragma unroll
    for (int s = 0; s < 4; s++) {
        #pragma unroll
        for (int i = 0; i < 2; i++) {
            const int vloc = s * 32 + ty + i * 16 + (vh << 3);
            const int v = v0 + vloc;
            if (v < FV_DHW) {
                const float2 f2 = make_float2(tile[2 * c2][vloc], tile[2 * c2 + 1][vloc]);
                outp[(size_t)v * 16 + c2] = __float22half2_rn(f2);
            }
        }
    }
}

// Accumulate one corner: 8B load (4 fp16 channels), fp32 fmaf.
static __device__ __forceinline__ void fv_acc_corner(
    float4& acc, const uint2* __restrict__ f, int vox, float wgt
) {
    uint2 u = __ldg(&f[(size_t)vox * 8]);
    const __half2 h0 = *reinterpret_cast<const __half2*>(&u.x);
    const __half2 h1 = *reinterpret_cast<const __half2*>(&u.y);
    const float2 a = __half22float2(h0);
    const float2 b = __half22float2(h1);
    acc.x = fmaf(wgt, a.x, acc.x);
    acc.y = fmaf(wgt, a.y, acc.y);
    acc.z = fmaf(wgt, b.x, acc.z);
    acc.w = fmaf(wgt, b.y, acc.w);
}

// ---------------------------------------------------------------------------
// Sample one z-slab: 8 threads per point; thread g owns channels [4g, 4g+4).
// Only points with z0 in [zlo, zhi) do work; others exit right after the
// cooperative coord broadcast. Coords use default caching (re-read each pass;
// 12MB stays L2-resident after pass 1). Output: streaming STG.128.
// ---------------------------------------------------------------------------
__global__ __launch_bounds__(256) void fv_sample_kernel(
    const float* __restrict__ xs,   // [N, 3] coords
    float4* __restrict__ out,       // [N, 8] float4 == [N, 32] float
    int n, int zlo, int zhi
) {
    const int t    = blockIdx.x * blockDim.x + threadIdx.x;
    const int p    = t >> 3;
    const int g    = t & 7;                 // channel group within point
    const int lane = threadIdx.x & 31;
    const int base = lane & ~7;             // first lane of this point's group

    // Cooperative coord load: lane r in [0,3) of each group loads component r.
    float cload = 0.0f;
    if (p < n && g < 3) cload = __ldg(xs + 3 * (size_t)p + g);
    const float cx = __shfl_sync(0xffffffffu, cload, base + 0);  // -> W
    const float cy = __shfl_sync(0xffffffffu, cload, base + 1);  // -> H
    const float cz = __shfl_sync(0xffffffffu, cload, base + 2);  // -> D
    if (p >= n) return;

    // align_corners=True, border padding: i = clamp((c+1)*0.5*(S-1), 0, S-1)
    const float fz = fminf(fmaxf((cz + 1.0f) * 64.0f, 0.0f), 128.0f);
    const int z0 = (int)floorf(fz);
    if (z0 < zlo || z0 >= zhi) return;      // not this pass's slab

    const float fx = fminf(fmaxf((cx + 1.0f) * 64.0f, 0.0f), 128.0f);
    const float fy = fminf(fmaxf((cy + 1.0f) * 64.0f, 0.0f), 128.0f);

    const int x0 = (int)floorf(fx);
    const int y0 = (int)floorf(fy);
    const float tx = fx - (float)x0;
    const float ty = fy - (float)y0;
    const float tz = fz - (float)z0;
    const int x1 = min(x0 + 1, 128);
    const int y1 = min(y0 + 1, 128);
    const int z1 = min(z0 + 1, 128);

    const float wx0 = 1.0f - tx, wx1 = tx;
    const float wy0 = 1.0f - ty, wy1 = ty;
    const float wz0 = 1.0f - tz, wz1 = tz;

    // Row bases in voxel units: voxel(z,y,x) = (z*129 + y)*129 + x
    const int r00 = (z0 * FV_S + y0) * FV_S;
    const int r01 = (z0 * FV_S + y1) * FV_S;
    const int r10 = (z1 * FV_S + y0) * FV_S;
    const int r11 = (z1 * FV_S + y1) * FV_S;

    // uint2 (8B = 4 fp16) view offset by this thread's channel group.
    const uint2* __restrict__ f = reinterpret_cast<const uint2*>(g_fmT) + g;

    float4 acc = make_float4(0.0f, 0.0f, 0.0f, 0.0f);
    fv_acc_corner(acc, f, r00 + x0, wz0 * wy0 * wx0);
    fv_acc_corner(acc, f, r00 + x1, wz0 * wy0 * wx1);
    fv_acc_corner(acc, f, r01 + x0, wz0 * wy1 * wx0);
    fv_acc_corner(acc, f, r01 + x1, wz0 * wy1 * wx1);
    fv_acc_corner(acc, f, r10 + x0, wz1 * wy0 * wx0);
    fv_acc_corner(acc, f, r10 + x1, wz1 * wy0 * wx1);
    fv_acc_corner(acc, f, r11 + x0, wz1 * wy1 * wx0);
    fv_acc_corner(acc, f, r11 + x1, wz1 * wy1 * wx1);

    __stcs(&out[(size_t)p * 8 + g], acc);   // streaming: full 128B line per point
}

extern "C" void kernel_launch(void* const* d_in, const int* in_sizes, int n_in,
                              void* d_out, int out_size) {
    const float* x  = (const float*)d_in[0];   // [N, 3]
    const float* fm = (const float*)d_in[1];   // [32, 129, 129, 129]
    const int n = in_sizes[0] / 3;

    // 1) Transpose + fp16 quantize to channel-last scratch.
    fv_transpose_kernel<<<(FV_DHW + TVOX - 1) / TVOX, dim3(32, 8)>>>(fm);

    // 2) Gather + trilinear blend, one z-slab at a time (L2-resident slabs).
    const int total  = n * 8;
    const int blocks = (total + 255) / 256;
    fv_sample_kernel<<<blocks, 256>>>(x, (float4*)d_out, n,  0,  32);
    fv_sample_kernel<<<blocks, 256>>>(x, (float4*)d_out, n, 32,  64);
    fv_sample_kernel<<<blocks, 256>>>(x, (float4*)d_out, n, 64,  96);
    fv_sample_kernel<<<blocks, 256>>>(x, (float4*)d_out, n, 96, 129);
}